// round 8
// baseline (speedup 1.0000x reference)
#include <cuda_runtime.h>
#include <cuda_fp16.h>
#include <cstdint>

// ---------------- problem constants ----------------
constexpr int B_    = 4;
constexpr int T_    = 16;
constexpr int C_    = 256;
constexpr int HEADS = 8;
constexpr int DH    = 32;
constexpr int HW    = 1024;       // 32*32
constexpr int NSLAB = B_ * T_;    // 64
constexpr float QSCALE = 0.17677669529663687f;
constexpr float LOSC   = 1024.0f;       // lo-operand pre-scale (exact pow2)
constexpr float LOSC_I = 1.0f / 1024.0f;

// ---------------- scratch (__device__ globals) ----------------
__device__ __half g_xhi[NSLAB * HW * C_];   // [slab][hw][c]
__device__ __half g_xlo[NSLAB * HW * C_];   // (f - hi) * 1024
__device__ __half g_whi[768 * 256];         // [o][c]
__device__ __half g_wlo[768 * 256];
__device__ __half g_wohi[256 * 256];
__device__ __half g_wolo[256 * 256];
__device__ float g_q[B_ * HEADS * T_ * DH * HW];   // [b][head][t][d][hw]
__device__ float g_k[B_ * HEADS * T_ * DH * HW];
__device__ float g_v[B_ * HEADS * T_ * DH * HW];
__device__ __half g_ohi[NSLAB * HW * C_];   // [slab][hw][e]
__device__ __half g_olo[NSLAB * HW * C_];   // scaled by 1024

// ---------------- PTX helpers ----------------
__device__ __forceinline__ uint32_t smem_u32(const void* p) {
    uint32_t a;
    asm("{ .reg .u64 t; cvta.to.shared.u64 t, %1; cvt.u32.u64 %0, t; }" : "=r"(a) : "l"(p));
    return a;
}
__device__ __forceinline__ void cp16(uint32_t s, const void* g) {
    asm volatile("cp.async.cg.shared.global [%0], [%1], 16;" :: "r"(s), "l"(g) : "memory");
}
__device__ __forceinline__ void cp_commit() {
    asm volatile("cp.async.commit_group;" ::: "memory");
}
template <int N>
__device__ __forceinline__ void cp_wait() {
    asm volatile("cp.async.wait_group %0;" :: "n"(N) : "memory");
}
__device__ __forceinline__ void ldsm4(uint32_t& r0, uint32_t& r1, uint32_t& r2,
                                      uint32_t& r3, uint32_t a) {
    asm volatile("ldmatrix.sync.aligned.m8n8.x4.shared.b16 {%0,%1,%2,%3}, [%4];"
                 : "=r"(r0), "=r"(r1), "=r"(r2), "=r"(r3) : "r"(a));
}
// f32-accumulating HMMA (main term)
__device__ __forceinline__ void mma_f32(float& c0, float& c1, float& c2, float& c3,
                                        uint32_t a0, uint32_t a1, uint32_t a2,
                                        uint32_t a3, uint32_t b0, uint32_t b1) {
    asm volatile(
        "mma.sync.aligned.m16n8k16.row.col.f32.f16.f16.f32 "
        "{%0,%1,%2,%3}, {%4,%5,%6,%7}, {%8,%9}, {%0,%1,%2,%3};"
        : "+f"(c0), "+f"(c1), "+f"(c2), "+f"(c3)
        : "r"(a0), "r"(a1), "r"(a2), "r"(a3), "r"(b0), "r"(b1));
}
// f16-accumulating HMMA (cross terms, 2x rate)
__device__ __forceinline__ void mma_f16(uint32_t& d0, uint32_t& d1,
                                        uint32_t a0, uint32_t a1, uint32_t a2,
                                        uint32_t a3, uint32_t b0, uint32_t b1) {
    asm volatile(
        "mma.sync.aligned.m16n8k16.row.col.f16.f16.f16.f16 "
        "{%0,%1}, {%2,%3,%4,%5}, {%6,%7}, {%0,%1};"
        : "+r"(d0), "+r"(d1)
        : "r"(a0), "r"(a1), "r"(a2), "r"(a3), "r"(b0), "r"(b1));
}

// ---------------- SMEM staging layout (swizzled, no padding) ----------------
// Row = 32 halves = 64B = 4 chunks of 16B. Chunk stored at (c ^ ((row>>1)&3)).
constexpr int O_AHI = 0;
constexpr int O_ALO = 8192;
constexpr int O_BHI = 16384;
constexpr int O_BLO = 20480;
constexpr int STAGE = 24576;
constexpr int NSTG  = 3;
constexpr int SMEM_TOTAL = NSTG * STAGE;    // 73728 (epilogue reuses)
constexpr int CSTR = 132;                   // C smem row stride (floats)

__device__ __forceinline__ uint32_t swz(int row, int chunk) {
    return (uint32_t)(row * 64 + ((chunk ^ ((row >> 1) & 3)) << 4));
}

// ================= tensor-core GEMM =================
// D[hw 128, o 64] = A[hw, K] * B[o, K]^T, K=256, fp16 hi/lo split.
// Main term f32-acc HMMA; cross terms share one f16-acc (lo pre-scaled 2^10).
// 128 threads, 4 warps (2m x 2n), warp tile 64x32, 3-stage cp.async, 3 CTAs/SM.
template <int EPI>
__global__ __launch_bounds__(128, 3) void mma_gemm(const __half* __restrict__ Ahig,
                                                   const __half* __restrict__ Alog,
                                                   const __half* __restrict__ Bhig,
                                                   const __half* __restrict__ Blog,
                                                   const float* __restrict__ bias,
                                                   float* __restrict__ Y) {
    extern __shared__ __align__(1024) char smem[];
    const uint32_t sb = smem_u32(smem);
    const int tid  = threadIdx.x;
    const int wid  = tid >> 5;
    const int lane = tid & 31;
    const int wm = wid & 1;     // warp m tile (64 rows)
    const int wn = wid >> 1;    // warp n tile (32 cols)

    const int slab = blockIdx.z;
    const int hw0  = blockIdx.x * 128;
    const int n0   = blockIdx.y * 64;

    const __half* ah = Ahig + ((size_t)slab * HW + hw0) * 256;
    const __half* al = Alog + ((size_t)slab * HW + hw0) * 256;
    const __half* bh = Bhig + (size_t)n0 * 256;
    const __half* bl = Blog + (size_t)n0 * 256;

    // hoisted ldmatrix base addresses (kk=0, stage 0); XOR-linear swizzle:
    // kk=1 -> ^0x20, B frag2 -> ^0x10, lo operand -> +8192/+4096, stage -> +rso
    const int rowA0 = wm * 64 + (lane & 15);
    const int chA   = lane >> 4;
    const int rowB  = wn * 32 + lane;
    const uint32_t adrA[4] = {
        sb + O_AHI + swz(rowA0,      chA),
        sb + O_AHI + swz(rowA0 + 16, chA),
        sb + O_AHI + swz(rowA0 + 32, chA),
        sb + O_AHI + swz(rowA0 + 48, chA)};
    const uint32_t adrB = sb + O_BHI + swz(rowB, 0);

    float acc[4][4][4];
    uint32_t accx[4][4][2];
#pragma unroll
    for (int mt = 0; mt < 4; mt++)
#pragma unroll
        for (int nt = 0; nt < 4; nt++) {
#pragma unroll
            for (int r = 0; r < 4; r++) acc[mt][nt][r] = 0.0f;
            accx[mt][nt][0] = 0u;
            accx[mt][nt][1] = 0u;
        }

    // cp.async mapping: row rA (+32v), chunk sA
    const int rA = tid >> 2, sA = tid & 3;
    const int rswIO = (rA >> 1) & 3;
    const uint32_t soIO = (uint32_t)(rA * 64 + ((sA ^ rswIO) << 4));

    auto issue = [&](int kt, uint32_t soff) {
        const uint32_t base = sb + soff;
        const int kbase = kt * 32;
#pragma unroll
        for (int v = 0; v < 4; v++) {       // A rows rA + 32v
            const uint32_t so = soIO + (uint32_t)(v * 2048);
            const size_t go = (size_t)(rA + 32 * v) * 256 + kbase + sA * 8;
            cp16(base + O_AHI + so, ah + go);
            cp16(base + O_ALO + so, al + go);
        }
#pragma unroll
        for (int v = 0; v < 2; v++) {       // B rows rA + 32v
            const uint32_t so = soIO + (uint32_t)(v * 2048);
            const size_t go = (size_t)(rA + 32 * v) * 256 + kbase + sA * 8;
            cp16(base + O_BHI + so, bh + go);
            cp16(base + O_BLO + so, bl + go);
        }
    };

    issue(0, 0);           cp_commit();
    issue(1, STAGE);       cp_commit();

    uint32_t rso = 0, wso = 2 * STAGE;
    for (int kt = 0; kt < 8; kt++) {
        if (kt < 7) cp_wait<1>(); else cp_wait<0>();
        __syncthreads();   // single barrier per kt (3-stage safety)
        if (kt < 6) {
            issue(kt + 2, wso);
            cp_commit();
            wso += STAGE; if (wso == NSTG * STAGE) wso = 0;
        }

#pragma unroll
        for (int kk = 0; kk < 2; kk++) {
            const uint32_t kx = (uint32_t)(kk << 5);
            uint32_t ahi[4][4], alo[4][4];
            uint32_t b0h[4], b1h[4], b0l[4], b1l[4];
#pragma unroll
            for (int mt = 0; mt < 4; mt++)
                ldsm4(ahi[mt][0], ahi[mt][1], ahi[mt][2], ahi[mt][3],
                      (adrA[mt] ^ kx) + rso);
            {
                const uint32_t bb = (adrB ^ kx) + rso;
                ldsm4(b0h[0], b0h[1], b0h[2], b0h[3], bb);
                ldsm4(b1h[0], b1h[1], b1h[2], b1h[3], bb ^ 0x10);
                ldsm4(b0l[0], b0l[1], b0l[2], b0l[3], bb + 4096);
                ldsm4(b1l[0], b1l[1], b1l[2], b1l[3], (bb ^ 0x10) + 4096);
            }
            // main term: f32 accumulate
#pragma unroll
            for (int mt = 0; mt < 4; mt++)
#pragma unroll
                for (int nt = 0; nt < 4; nt++)
                    mma_f32(acc[mt][nt][0], acc[mt][nt][1], acc[mt][nt][2],
                            acc[mt][nt][3], ahi[mt][0], ahi[mt][1], ahi[mt][2],
                            ahi[mt][3], b0h[nt], b1h[nt]);
            // cross term 1: A_hi * B_lo' (f16 acc)
#pragma unroll
            for (int mt = 0; mt < 4; mt++)
#pragma unroll
                for (int nt = 0; nt < 4; nt++)
                    mma_f16(accx[mt][nt][0], accx[mt][nt][1],
                            ahi[mt][0], ahi[mt][1], ahi[mt][2], ahi[mt][3],
                            b0l[nt], b1l[nt]);
            // cross term 2: A_lo' * B_hi (f16 acc, same scale 2^10)
#pragma unroll
            for (int mt = 0; mt < 4; mt++)
                ldsm4(alo[mt][0], alo[mt][1], alo[mt][2], alo[mt][3],
                      (adrA[mt] ^ kx) + rso + 8192);
#pragma unroll
            for (int mt = 0; mt < 4; mt++)
#pragma unroll
                for (int nt = 0; nt < 4; nt++)
                    mma_f16(accx[mt][nt][0], accx[mt][nt][1],
                            alo[mt][0], alo[mt][1], alo[mt][2], alo[mt][3],
                            b0h[nt], b1h[nt]);
        }
        rso += STAGE; if (rso == NSTG * STAGE) rso = 0;
    }
    __syncthreads();

    // ---------------- epilogue: merge cross terms, transpose through SMEM ----
    float* cs = (float*)smem;   // [64 n][CSTR m]
#pragma unroll
    for (int mt = 0; mt < 4; mt++)
#pragma unroll
        for (int nt = 0; nt < 4; nt++) {
            const __half2 x01 = *(__half2*)&accx[mt][nt][0];
            const __half2 x23 = *(__half2*)&accx[mt][nt][1];
            const float2 f01 = __half22float2(x01);
            const float2 f23 = __half22float2(x23);
            const int n = wn * 32 + nt * 8 + (lane & 3) * 2;
            const int m = wm * 64 + mt * 16 + (lane >> 2);
            cs[n * CSTR + m]           = acc[mt][nt][0] + f01.x * LOSC_I;
            cs[(n + 1) * CSTR + m]     = acc[mt][nt][1] + f01.y * LOSC_I;
            cs[n * CSTR + m + 8]       = acc[mt][nt][2] + f23.x * LOSC_I;
            cs[(n + 1) * CSTR + m + 8] = acc[mt][nt][3] + f23.y * LOSC_I;
        }
    __syncthreads();

    const int b_ = slab >> 4, t_ = slab & 15;
#pragma unroll
    for (int r = 0; r < 16; r++) {
        const int n = wid * 16 + r;
        const int o = n0 + n;
        float4 v = *(const float4*)&cs[n * CSTR + lane * 4];
        const float bv = bias[o];
        if (EPI == 0) {
            const int which = o >> 8;
            const int head  = (o >> 5) & 7;
            const int d     = o & 31;
            float* dst = (which == 0) ? g_q : (which == 1 ? g_k : g_v);
            const float sc = (which == 0) ? QSCALE : 1.0f;
            v.x = (v.x + bv) * sc; v.y = (v.y + bv) * sc;
            v.z = (v.z + bv) * sc; v.w = (v.w + bv) * sc;
            const size_t off =
                ((size_t)(((b_ * 8 + head) * 16 + t_) * 32 + d)) * 1024 + hw0 + lane * 4;
            *(float4*)(dst + off) = v;
        } else {
            v.x += bv; v.y += bv; v.z += bv; v.w += bv;
            *(float4*)(Y + ((size_t)slab * 256 + o) * 1024 + hw0 + lane * 4) = v;
        }
    }
}

// ================= split / transpose kernels =================
__global__ __launch_bounds__(256) void split_k(const float* __restrict__ s,
                                               __half* __restrict__ hi,
                                               __half* __restrict__ lo, int n) {
    const int i = blockIdx.x * 256 + threadIdx.x;
    if (i < n) {
        const float f = s[i];
        const __half h = __float2half_rn(f);
        hi[i] = h;
        lo[i] = __float2half_rn((f - __half2float(h)) * LOSC);
    }
}

// x [slab][c][hw] f32 -> g_xhi/g_xlo [slab][hw][c] fp16 split (64x64 tiles)
__global__ __launch_bounds__(256) void split_x_k(const float* __restrict__ x) {
    __shared__ float ts[64][65];
    const int slab = blockIdx.z;
    const int c0 = blockIdx.y * 64;
    const int h0 = blockIdx.x * 64;
    const int tid = threadIdx.x;
    const int r = tid >> 2;
    const int q4 = tid & 3;

    const float* src = x + ((size_t)slab * 256 + c0 + r) * 1024 + h0 + q4 * 16;
#pragma unroll
    for (int j = 0; j < 4; j++) {
        const float4 v = *(const float4*)(src + j * 4);
        ts[r][q4 * 16 + j * 4 + 0] = v.x;
        ts[r][q4 * 16 + j * 4 + 1] = v.y;
        ts[r][q4 * 16 + j * 4 + 2] = v.z;
        ts[r][q4 * 16 + j * 4 + 3] = v.w;
    }
    __syncthreads();

    __half hb[16], lb[16];
#pragma unroll
    for (int j = 0; j < 16; j++) {
        const float f = ts[q4 * 16 + j][r];
        const __half h = __float2half_rn(f);
        hb[j] = h;
        lb[j] = __float2half_rn((f - __half2float(h)) * LOSC);
    }
    const size_t o = ((size_t)slab * 1024 + h0 + r) * 256 + c0 + q4 * 16;
    *(uint4*)(g_xhi + o)     = ((uint4*)hb)[0];
    *(uint4*)(g_xhi + o + 8) = ((uint4*)hb)[1];
    *(uint4*)(g_xlo + o)     = ((uint4*)lb)[0];
    *(uint4*)(g_xlo + o + 8) = ((uint4*)lb)[1];
}

// ================= attention (T=16), f32 in, fp16-split out =================
__device__ __forceinline__ unsigned long long pack2(float lo, float hi) {
    unsigned long long r;
    asm("mov.b64 %0, {%1, %2};" : "=l"(r) : "f"(lo), "f"(hi));
    return r;
}
__device__ __forceinline__ void unpack2(unsigned long long p, float& lo, float& hi) {
    asm("mov.b64 {%0, %1}, %2;" : "=f"(lo), "=f"(hi) : "l"(p));
}
__device__ __forceinline__ unsigned long long ffma2(unsigned long long a,
                                                    unsigned long long b,
                                                    unsigned long long c) {
    unsigned long long d;
    asm("fma.rn.f32x2 %0, %1, %2, %3;" : "=l"(d) : "l"(a), "l"(b), "l"(c));
    return d;
}

constexpr int KVP = 512 + 4;
__global__ __launch_bounds__(128) void attn_k(const float* __restrict__ rel_pos) {
    __shared__ __align__(16) float k_s[8][KVP];
    __shared__ __align__(16) float v_s[8][KVP];

    const int bh  = blockIdx.y;
    const int hw0 = blockIdx.x * 8;
    const int tid = threadIdx.x;
    const int hwl = tid & 7;
    const int i   = tid >> 3;

    const size_t ubase = (size_t)bh * 512 * HW;

    for (int e = tid; e < 4096; e += 128) {
        const int td = e >> 3;
        const int hw = e & 7;
        k_s[hw][td] = g_k[ubase + (size_t)td * HW + hw0 + hw];
        v_s[hw][td] = g_v[ubase + (size_t)td * HW + hw0 + hw];
    }
    __syncthreads();

    unsigned long long qp[16];
    const size_t qbase = ubase + (size_t)i * 32 * HW + hw0 + hwl;
#pragma unroll
    for (int c = 0; c < 16; c++)
        qp[c] = pack2(g_q[qbase + (size_t)(2 * c) * HW],
                      g_q[qbase + (size_t)(2 * c + 1) * HW]);

    const int head = bh & 7;
    const float* rp = rel_pos + head * 256 + i * 16;

    float s[16];
#pragma unroll
    for (int j = 0; j < 16; j++) {
        const ulonglong2* kp = (const ulonglong2*)&k_s[hwl][j * 32];
        unsigned long long acc = 0ull;
#pragma unroll
        for (int c = 0; c < 8; c++) {
            const ulonglong2 kk = kp[c];
            acc = ffma2(qp[2 * c],     kk.x, acc);
            acc = ffma2(qp[2 * c + 1], kk.y, acc);
        }
        float lo, hi;
        unpack2(acc, lo, hi);
        s[j] = lo + hi + rp[j];
    }

    float mx = s[0];
#pragma unroll
    for (int j = 1; j < 16; j++) mx = fmaxf(mx, s[j]);
    float sum = 0.0f;
#pragma unroll
    for (int j = 0; j < 16; j++) { s[j] = expf(s[j] - mx); sum += s[j]; }
    const float inv = 1.0f / sum;

    unsigned long long o2[16];
#pragma unroll
    for (int c = 0; c < 16; c++) o2[c] = 0ull;
#pragma unroll
    for (int j = 0; j < 16; j++) {
        const unsigned long long pp = pack2(s[j], s[j]);
        const ulonglong2* vp = (const ulonglong2*)&v_s[hwl][j * 32];
#pragma unroll
        for (int c = 0; c < 8; c++) {
            const ulonglong2 vv = vp[c];
            o2[2 * c]     = ffma2(pp, vv.x, o2[2 * c]);
            o2[2 * c + 1] = ffma2(pp, vv.y, o2[2 * c + 1]);
        }
    }

    // write fp16-split output [slab][hw][e] (lo scaled by 2^10)
    const int b_ = bh >> 3;
    const size_t obase =
        ((size_t)((b_ * 16 + i)) * 1024 + hw0 + hwl) * 256 + head * 32;
#pragma unroll
    for (int c = 0; c < 16; c++) {
        float lo, hi;
        unpack2(o2[c], lo, hi);
        const float v0 = lo * inv, v1 = hi * inv;
        const __half h0 = __float2half_rn(v0);
        const __half h1 = __float2half_rn(v1);
        const __half l0 = __float2half_rn((v0 - __half2float(h0)) * LOSC);
        const __half l1 = __float2half_rn((v1 - __half2float(h1)) * LOSC);
        ((__half2*)(g_ohi + obase))[c] = __halves2half2(h0, h1);
        ((__half2*)(g_olo + obase))[c] = __halves2half2(l0, l1);
    }
}

// ================= host =================
extern "C" void kernel_launch(void* const* d_in, const int* in_sizes, int n_in,
                              void* d_out, int out_size) {
    const float* x       = (const float*)d_in[0];
    const float* rel_pos = (const float*)d_in[1];
    const float* w_qkv   = (const float*)d_in[2];
    const float* b_qkv   = (const float*)d_in[3];
    const float* w_out   = (const float*)d_in[4];
    const float* b_out   = (const float*)d_in[5];
    float* y = (float*)d_out;

    cudaFuncSetAttribute(mma_gemm<0>, cudaFuncAttributeMaxDynamicSharedMemorySize, SMEM_TOTAL);
    cudaFuncSetAttribute(mma_gemm<1>, cudaFuncAttributeMaxDynamicSharedMemorySize, SMEM_TOTAL);

    __half *xhi, *xlo, *whi, *wlo, *wohi, *wolo, *ohi, *olo;
    cudaGetSymbolAddress((void**)&xhi, g_xhi);
    cudaGetSymbolAddress((void**)&xlo, g_xlo);
    cudaGetSymbolAddress((void**)&whi, g_whi);
    cudaGetSymbolAddress((void**)&wlo, g_wlo);
    cudaGetSymbolAddress((void**)&wohi, g_wohi);
    cudaGetSymbolAddress((void**)&wolo, g_wolo);
    cudaGetSymbolAddress((void**)&ohi, g_ohi);
    cudaGetSymbolAddress((void**)&olo, g_olo);

    // precision splits (lo pre-scaled by 2^10)
    split_k<<<768, 256>>>(w_qkv, whi, wlo, 768 * 256);
    split_k<<<256, 256>>>(w_out, wohi, wolo, 256 * 256);
    split_x_k<<<dim3(16, 4, 64), 256>>>(x);

    // QKV projection: grid = (hw tiles 8, o tiles 12, slabs 64)
    mma_gemm<0><<<dim3(8, 12, 64), 128, SMEM_TOTAL>>>(xhi, xlo, whi, wlo, b_qkv, nullptr);
    // attention
    attn_k<<<dim3(128, 32), 128>>>(rel_pos);
    // output projection: grid = (8, 4, 64)
    mma_gemm<1><<<dim3(8, 4, 64), 128, SMEM_TOTAL>>>(ohi, olo, wohi, wolo, b_out, y);
}

// round 9
// speedup vs baseline: 1.2008x; 1.2008x over previous
#include <cuda_runtime.h>
#include <cuda_fp16.h>
#include <cstdint>

// ---------------- problem constants ----------------
constexpr int B_    = 4;
constexpr int T_    = 16;
constexpr int C_    = 256;
constexpr int HEADS = 8;
constexpr int DH    = 32;
constexpr int HW    = 1024;       // 32*32
constexpr int NSLAB = B_ * T_;    // 64
constexpr float QSCALE = 0.17677669529663687f;

// ---------------- scratch (__device__ globals) ----------------
__device__ __half g_xhi[NSLAB * HW * C_];   // [slab][hw][c]
__device__ __half g_xlo[NSLAB * HW * C_];
__device__ __half g_whi[768 * 256];         // [o][c]
__device__ __half g_wlo[768 * 256];
__device__ __half g_wohi[256 * 256];
__device__ float g_q[B_ * HEADS * T_ * DH * HW];   // [b][head][t][d][hw]
__device__ float g_k[B_ * HEADS * T_ * DH * HW];
__device__ float g_v[B_ * HEADS * T_ * DH * HW];
__device__ __half g_ohi[NSLAB * HW * C_];   // [slab][hw][e]

// ---------------- PTX helpers ----------------
__device__ __forceinline__ uint32_t smem_u32(const void* p) {
    uint32_t a;
    asm("{ .reg .u64 t; cvta.to.shared.u64 t, %1; cvt.u32.u64 %0, t; }" : "=r"(a) : "l"(p));
    return a;
}
__device__ __forceinline__ void cp16(uint32_t s, const void* g) {
    asm volatile("cp.async.cg.shared.global [%0], [%1], 16;" :: "r"(s), "l"(g) : "memory");
}
__device__ __forceinline__ void cp_commit() {
    asm volatile("cp.async.commit_group;" ::: "memory");
}
template <int N>
__device__ __forceinline__ void cp_wait() {
    asm volatile("cp.async.wait_group %0;" :: "n"(N) : "memory");
}
__device__ __forceinline__ void ldsm4(uint32_t& r0, uint32_t& r1, uint32_t& r2,
                                      uint32_t& r3, uint32_t a) {
    asm volatile("ldmatrix.sync.aligned.m8n8.x4.shared.b16 {%0,%1,%2,%3}, [%4];"
                 : "=r"(r0), "=r"(r1), "=r"(r2), "=r"(r3) : "r"(a));
}
__device__ __forceinline__ void mma16816(float& c0, float& c1, float& c2, float& c3,
                                         uint32_t a0, uint32_t a1, uint32_t a2,
                                         uint32_t a3, uint32_t b0, uint32_t b1) {
    asm volatile(
        "mma.sync.aligned.m16n8k16.row.col.f32.f16.f16.f32 "
        "{%0,%1,%2,%3}, {%4,%5,%6,%7}, {%8,%9}, {%0,%1,%2,%3};"
        : "+f"(c0), "+f"(c1), "+f"(c2), "+f"(c3)
        : "r"(a0), "r"(a1), "r"(a2), "r"(a3), "r"(b0), "r"(b1));
}

// ---------------- SMEM staging layout (swizzled, no padding) ----------------
// Row = 32 halves = 64B = 4 chunks of 16B. Chunk stored at (c ^ ((row>>1)&3)).
constexpr int O_AHI = 0;
constexpr int O_ALO = 8192;
constexpr int O_BHI = 16384;
constexpr int O_BLO = 20480;
constexpr int STAGE = 24576;
constexpr int SMEM_TOTAL = 2 * STAGE;       // 49152 (epilogue reuses)
constexpr int CSTR = 132;                   // C smem row stride (floats)

__device__ __forceinline__ uint32_t swz(int row, int chunk) {
    return (uint32_t)(row * 64 + ((chunk ^ ((row >> 1) & 3)) << 4));
}

// ================= tensor-core GEMM =================
// D[hw 128, o 64] = A[hw, K] * B[o, K]^T, K=256.
// PASSES==3: fp16 hi/lo 3-term split (f32 acc). PASSES==1: plain fp16 hi*hi.
// 128 threads, 4 warps (2m x 2n), warp tile 64x32, 2-stage cp.async, 4 CTAs/SM.
template <int EPI, int PASSES>
__global__ __launch_bounds__(128, 4) void mma_gemm(const __half* __restrict__ Ahig,
                                                   const __half* __restrict__ Alog,
                                                   const __half* __restrict__ Bhig,
                                                   const __half* __restrict__ Blog,
                                                   const float* __restrict__ bias,
                                                   float* __restrict__ Y) {
    extern __shared__ __align__(1024) char smem[];
    const uint32_t sb = smem_u32(smem);
    const int tid  = threadIdx.x;
    const int wid  = tid >> 5;
    const int lane = tid & 31;
    const int wm = wid & 1;     // warp m tile (64 rows)
    const int wn = wid >> 1;    // warp n tile (32 cols)

    const int slab = blockIdx.z;
    const int hw0  = blockIdx.x * 128;
    const int n0   = blockIdx.y * 64;

    const __half* ah = Ahig + ((size_t)slab * HW + hw0) * 256;
    const __half* al = (PASSES == 3) ? Alog + ((size_t)slab * HW + hw0) * 256 : ah;
    const __half* bh = Bhig + (size_t)n0 * 256;
    const __half* bl = (PASSES == 3) ? Blog + (size_t)n0 * 256 : bh;

    // hoisted ldmatrix base addresses (kk=0, stage 0); XOR-linear swizzle:
    // kk=1 -> ^0x20, B frag2 -> ^0x10, lo operand -> +8192/+4096, stage -> +so
    const int rowA0 = wm * 64 + (lane & 15);
    const int chA   = lane >> 4;
    const int rowB  = wn * 32 + lane;
    const uint32_t adrA[4] = {
        sb + O_AHI + swz(rowA0,      chA),
        sb + O_AHI + swz(rowA0 + 16, chA),
        sb + O_AHI + swz(rowA0 + 32, chA),
        sb + O_AHI + swz(rowA0 + 48, chA)};
    const uint32_t adrB = sb + O_BHI + swz(rowB, 0);

    float acc[4][4][4];
#pragma unroll
    for (int mt = 0; mt < 4; mt++)
#pragma unroll
        for (int nt = 0; nt < 4; nt++)
#pragma unroll
            for (int r = 0; r < 4; r++) acc[mt][nt][r] = 0.0f;

    // cp.async mapping: row rA (+32v), chunk sA
    const int rA = tid >> 2, sA = tid & 3;
    const int rswIO = (rA >> 1) & 3;
    const uint32_t soIO = (uint32_t)(rA * 64 + ((sA ^ rswIO) << 4));

    auto issue = [&](int kt, int s) {
        const uint32_t base = sb + s * STAGE;
        const int kbase = kt * 32;
#pragma unroll
        for (int v = 0; v < 4; v++) {       // A rows rA + 32v
            const uint32_t so = soIO + (uint32_t)(v * 2048);
            const size_t go = (size_t)(rA + 32 * v) * 256 + kbase + sA * 8;
            cp16(base + O_AHI + so, ah + go);
            if (PASSES == 3) cp16(base + O_ALO + so, al + go);
        }
#pragma unroll
        for (int v = 0; v < 2; v++) {       // B rows rA + 32v
            const uint32_t so = soIO + (uint32_t)(v * 2048);
            const size_t go = (size_t)(rA + 32 * v) * 256 + kbase + sA * 8;
            cp16(base + O_BHI + so, bh + go);
            if (PASSES == 3) cp16(base + O_BLO + so, bl + go);
        }
    };

    issue(0, 0);
    cp_commit();

    uint32_t so = 0;   // stage offset, toggles 0 <-> STAGE
    for (int kt = 0; kt < 8; kt++) {
        if (kt < 7) {
            issue(kt + 1, (kt + 1) & 1);
            cp_commit();
            cp_wait<1>();
        } else {
            cp_wait<0>();
        }
        __syncthreads();

#pragma unroll
        for (int kk = 0; kk < 2; kk++) {
            const uint32_t kx = (uint32_t)(kk << 5);   // kk=1 -> ^0x20
            uint32_t ahi[4][4];
            uint32_t b0h[4], b1h[4];
#pragma unroll
            for (int mt = 0; mt < 4; mt++)
                ldsm4(ahi[mt][0], ahi[mt][1], ahi[mt][2], ahi[mt][3],
                      (adrA[mt] ^ kx) + so);
            const uint32_t bb = (adrB ^ kx) + so;
            ldsm4(b0h[0], b0h[1], b0h[2], b0h[3], bb);
            ldsm4(b1h[0], b1h[1], b1h[2], b1h[3], bb ^ 0x10);

            if (PASSES == 3) {
                uint32_t b0l[4], b1l[4], alo[4][4];
                ldsm4(b0l[0], b0l[1], b0l[2], b0l[3], bb + 4096);
                ldsm4(b1l[0], b1l[1], b1l[2], b1l[3], (bb ^ 0x10) + 4096);
#pragma unroll
                for (int mt = 0; mt < 4; mt++)
#pragma unroll
                    for (int nt = 0; nt < 4; nt++)
                        mma16816(acc[mt][nt][0], acc[mt][nt][1], acc[mt][nt][2],
                                 acc[mt][nt][3], ahi[mt][0], ahi[mt][1],
                                 ahi[mt][2], ahi[mt][3], b0h[nt], b1h[nt]);
#pragma unroll
                for (int mt = 0; mt < 4; mt++)
#pragma unroll
                    for (int nt = 0; nt < 4; nt++)
                        mma16816(acc[mt][nt][0], acc[mt][nt][1], acc[mt][nt][2],
                                 acc[mt][nt][3], ahi[mt][0], ahi[mt][1],
                                 ahi[mt][2], ahi[mt][3], b0l[nt], b1l[nt]);
#pragma unroll
                for (int mt = 0; mt < 4; mt++)
                    ldsm4(alo[mt][0], alo[mt][1], alo[mt][2], alo[mt][3],
                          (adrA[mt] ^ kx) + so + 8192);
#pragma unroll
                for (int mt = 0; mt < 4; mt++)
#pragma unroll
                    for (int nt = 0; nt < 4; nt++)
                        mma16816(acc[mt][nt][0], acc[mt][nt][1], acc[mt][nt][2],
                                 acc[mt][nt][3], alo[mt][0], alo[mt][1],
                                 alo[mt][2], alo[mt][3], b0h[nt], b1h[nt]);
            } else {
#pragma unroll
                for (int mt = 0; mt < 4; mt++)
#pragma unroll
                    for (int nt = 0; nt < 4; nt++)
                        mma16816(acc[mt][nt][0], acc[mt][nt][1], acc[mt][nt][2],
                                 acc[mt][nt][3], ahi[mt][0], ahi[mt][1],
                                 ahi[mt][2], ahi[mt][3], b0h[nt], b1h[nt]);
            }
        }
        __syncthreads();
        so ^= (uint32_t)STAGE;
    }

    // ---------------- epilogue: transpose through SMEM ----------------
    float* cs = (float*)smem;   // [64 n][CSTR m]
#pragma unroll
    for (int mt = 0; mt < 4; mt++)
#pragma unroll
        for (int nt = 0; nt < 4; nt++) {
            const int n = wn * 32 + nt * 8 + (lane & 3) * 2;
            const int m = wm * 64 + mt * 16 + (lane >> 2);
            cs[n * CSTR + m]           = acc[mt][nt][0];
            cs[(n + 1) * CSTR + m]     = acc[mt][nt][1];
            cs[n * CSTR + m + 8]       = acc[mt][nt][2];
            cs[(n + 1) * CSTR + m + 8] = acc[mt][nt][3];
        }
    __syncthreads();

    const int b_ = slab >> 4, t_ = slab & 15;
#pragma unroll
    for (int r = 0; r < 16; r++) {
        const int n = wid * 16 + r;
        const int o = n0 + n;
        float4 v = *(const float4*)&cs[n * CSTR + lane * 4];
        const float bv = bias[o];
        if (EPI == 0) {
            const int which = o >> 8;
            const int head  = (o >> 5) & 7;
            const int d     = o & 31;
            float* dst = (which == 0) ? g_q : (which == 1 ? g_k : g_v);
            const float sc = (which == 0) ? QSCALE : 1.0f;
            v.x = (v.x + bv) * sc; v.y = (v.y + bv) * sc;
            v.z = (v.z + bv) * sc; v.w = (v.w + bv) * sc;
            const size_t off =
                ((size_t)(((b_ * 8 + head) * 16 + t_) * 32 + d)) * 1024 + hw0 + lane * 4;
            *(float4*)(dst + off) = v;
        } else {
            v.x += bv; v.y += bv; v.z += bv; v.w += bv;
            *(float4*)(Y + ((size_t)slab * 256 + o) * 1024 + hw0 + lane * 4) = v;
        }
    }
}

// ================= split / transpose kernels =================
__global__ __launch_bounds__(256) void split_k(const float* __restrict__ s,
                                               __half* __restrict__ hi,
                                               __half* __restrict__ lo, int n) {
    const int i = blockIdx.x * 256 + threadIdx.x;
    if (i < n) {
        const float f = s[i];
        const __half h = __float2half_rn(f);
        hi[i] = h;
        if (lo) lo[i] = __float2half_rn(f - __half2float(h));
    }
}

// x [slab][c][hw] f32 -> g_xhi/g_xlo [slab][hw][c] fp16 split (64x64 tiles)
__global__ __launch_bounds__(256) void split_x_k(const float* __restrict__ x) {
    __shared__ float ts[64][65];
    const int slab = blockIdx.z;
    const int c0 = blockIdx.y * 64;
    const int h0 = blockIdx.x * 64;
    const int tid = threadIdx.x;
    const int r = tid >> 2;
    const int q4 = tid & 3;

    const float* src = x + ((size_t)slab * 256 + c0 + r) * 1024 + h0 + q4 * 16;
#pragma unroll
    for (int j = 0; j < 4; j++) {
        const float4 v = *(const float4*)(src + j * 4);
        ts[r][q4 * 16 + j * 4 + 0] = v.x;
        ts[r][q4 * 16 + j * 4 + 1] = v.y;
        ts[r][q4 * 16 + j * 4 + 2] = v.z;
        ts[r][q4 * 16 + j * 4 + 3] = v.w;
    }
    __syncthreads();

    __half hb[16], lb[16];
#pragma unroll
    for (int j = 0; j < 16; j++) {
        const float f = ts[q4 * 16 + j][r];
        const __half h = __float2half_rn(f);
        hb[j] = h;
        lb[j] = __float2half_rn(f - __half2float(h));
    }
    const size_t o = ((size_t)slab * 1024 + h0 + r) * 256 + c0 + q4 * 16;
    *(uint4*)(g_xhi + o)     = ((uint4*)hb)[0];
    *(uint4*)(g_xhi + o + 8) = ((uint4*)hb)[1];
    *(uint4*)(g_xlo + o)     = ((uint4*)lb)[0];
    *(uint4*)(g_xlo + o + 8) = ((uint4*)lb)[1];
}

// ================= attention (T=16), f32 in, fp16 out =================
__device__ __forceinline__ unsigned long long pack2(float lo, float hi) {
    unsigned long long r;
    asm("mov.b64 %0, {%1, %2};" : "=l"(r) : "f"(lo), "f"(hi));
    return r;
}
__device__ __forceinline__ void unpack2(unsigned long long p, float& lo, float& hi) {
    asm("mov.b64 {%0, %1}, %2;" : "=f"(lo), "=f"(hi) : "l"(p));
}
__device__ __forceinline__ unsigned long long ffma2(unsigned long long a,
                                                    unsigned long long b,
                                                    unsigned long long c) {
    unsigned long long d;
    asm("fma.rn.f32x2 %0, %1, %2, %3;" : "=l"(d) : "l"(a), "l"(b), "l"(c));
    return d;
}

constexpr int KVP = 512 + 4;
__global__ __launch_bounds__(128) void attn_k(const float* __restrict__ rel_pos) {
    __shared__ __align__(16) float k_s[8][KVP];
    __shared__ __align__(16) float v_s[8][KVP];

    const int bh  = blockIdx.y;
    const int hw0 = blockIdx.x * 8;
    const int tid = threadIdx.x;
    const int hwl = tid & 7;
    const int i   = tid >> 3;

    const size_t ubase = (size_t)bh * 512 * HW;

    for (int e = tid; e < 4096; e += 128) {
        const int td = e >> 3;
        const int hw = e & 7;
        k_s[hw][td] = g_k[ubase + (size_t)td * HW + hw0 + hw];
        v_s[hw][td] = g_v[ubase + (size_t)td * HW + hw0 + hw];
    }
    __syncthreads();

    unsigned long long qp[16];
    const size_t qbase = ubase + (size_t)i * 32 * HW + hw0 + hwl;
#pragma unroll
    for (int c = 0; c < 16; c++)
        qp[c] = pack2(g_q[qbase + (size_t)(2 * c) * HW],
                      g_q[qbase + (size_t)(2 * c + 1) * HW]);

    const int head = bh & 7;
    const float* rp = rel_pos + head * 256 + i * 16;

    float s[16];
#pragma unroll
    for (int j = 0; j < 16; j++) {
        const ulonglong2* kp = (const ulonglong2*)&k_s[hwl][j * 32];
        unsigned long long acc = 0ull;
#pragma unroll
        for (int c = 0; c < 8; c++) {
            const ulonglong2 kk = kp[c];
            acc = ffma2(qp[2 * c],     kk.x, acc);
            acc = ffma2(qp[2 * c + 1], kk.y, acc);
        }
        float lo, hi;
        unpack2(acc, lo, hi);
        s[j] = lo + hi + rp[j];
    }

    float mx = s[0];
#pragma unroll
    for (int j = 1; j < 16; j++) mx = fmaxf(mx, s[j]);
    float sum = 0.0f;
#pragma unroll
    for (int j = 0; j < 16; j++) { s[j] = expf(s[j] - mx); sum += s[j]; }
    const float inv = 1.0f / sum;

    unsigned long long o2[16];
#pragma unroll
    for (int c = 0; c < 16; c++) o2[c] = 0ull;
#pragma unroll
    for (int j = 0; j < 16; j++) {
        const unsigned long long pp = pack2(s[j], s[j]);
        const ulonglong2* vp = (const ulonglong2*)&v_s[hwl][j * 32];
#pragma unroll
        for (int c = 0; c < 8; c++) {
            const ulonglong2 vv = vp[c];
            o2[2 * c]     = ffma2(pp, vv.x, o2[2 * c]);
            o2[2 * c + 1] = ffma2(pp, vv.y, o2[2 * c + 1]);
        }
    }

    // write fp16 output [slab][hw][e]
    const int b_ = bh >> 3;
    const size_t obase =
        ((size_t)((b_ * 16 + i)) * 1024 + hw0 + hwl) * 256 + head * 32;
#pragma unroll
    for (int c = 0; c < 16; c++) {
        float lo, hi;
        unpack2(o2[c], lo, hi);
        ((__half2*)(g_ohi + obase))[c] =
            __halves2half2(__float2half_rn(lo * inv), __float2half_rn(hi * inv));
    }
}

// ================= host =================
extern "C" void kernel_launch(void* const* d_in, const int* in_sizes, int n_in,
                              void* d_out, int out_size) {
    const float* x       = (const float*)d_in[0];
    const float* rel_pos = (const float*)d_in[1];
    const float* w_qkv   = (const float*)d_in[2];
    const float* b_qkv   = (const float*)d_in[3];
    const float* w_out   = (const float*)d_in[4];
    const float* b_out   = (const float*)d_in[5];
    float* y = (float*)d_out;

    cudaFuncSetAttribute(mma_gemm<0, 3>, cudaFuncAttributeMaxDynamicSharedMemorySize, SMEM_TOTAL);
    cudaFuncSetAttribute(mma_gemm<1, 1>, cudaFuncAttributeMaxDynamicSharedMemorySize, SMEM_TOTAL);

    __half *xhi, *xlo, *whi, *wlo, *wohi, *ohi;
    cudaGetSymbolAddress((void**)&xhi, g_xhi);
    cudaGetSymbolAddress((void**)&xlo, g_xlo);
    cudaGetSymbolAddress((void**)&whi, g_whi);
    cudaGetSymbolAddress((void**)&wlo, g_wlo);
    cudaGetSymbolAddress((void**)&wohi, g_wohi);
    cudaGetSymbolAddress((void**)&ohi, g_ohi);

    // precision splits
    split_k<<<768, 256>>>(w_qkv, whi, wlo, 768 * 256);
    split_k<<<256, 256>>>(w_out, wohi, nullptr, 256 * 256);
    split_x_k<<<dim3(16, 4, 64), 256>>>(x);

    // QKV projection (3-term split): grid = (hw tiles 8, o tiles 12, slabs 64)
    mma_gemm<0, 3><<<dim3(8, 12, 64), 128, SMEM_TOTAL>>>(xhi, xlo, whi, wlo, b_qkv, nullptr);
    // attention
    attn_k<<<dim3(128, 32), 128>>>(rel_pos);
    // output projection (single fp16 pass): grid = (8, 4, 64)
    mma_gemm<1, 1><<<dim3(8, 4, 64), 128, SMEM_TOTAL>>>(ohi, nullptr, wohi, nullptr, b_out, y);
}

// round 10
// speedup vs baseline: 1.4329x; 1.1933x over previous
#include <cuda_runtime.h>
#include <cuda_fp16.h>
#include <cstdint>

// ---------------- problem constants ----------------
constexpr int B_    = 4;
constexpr int T_    = 16;
constexpr int C_    = 256;
constexpr int HEADS = 8;
constexpr int DH    = 32;
constexpr int HW    = 1024;       // 32*32
constexpr int NSLAB = B_ * T_;    // 64
constexpr float QSCALE = 0.17677669529663687f;

// ---------------- scratch (__device__ globals) ----------------
__device__ __half g_xhi[NSLAB * HW * C_];   // [slab][hw][c]
__device__ __half g_whi[768 * 256];         // [o][c]
__device__ __half g_wlo[768 * 256];
__device__ __half g_wohi[256 * 256];
__device__ float g_q[B_ * HEADS * T_ * DH * HW];   // [b][head][t][d][hw]
__device__ float g_k[B_ * HEADS * T_ * DH * HW];
__device__ float g_v[B_ * HEADS * T_ * DH * HW];
__device__ __half g_ohi[NSLAB * HW * C_];   // [slab][hw][e]

// ---------------- PTX helpers ----------------
__device__ __forceinline__ uint32_t smem_u32(const void* p) {
    uint32_t a;
    asm("{ .reg .u64 t; cvta.to.shared.u64 t, %1; cvt.u32.u64 %0, t; }" : "=r"(a) : "l"(p));
    return a;
}
__device__ __forceinline__ void cp16(uint32_t s, const void* g) {
    asm volatile("cp.async.cg.shared.global [%0], [%1], 16;" :: "r"(s), "l"(g) : "memory");
}
__device__ __forceinline__ void cp_commit() {
    asm volatile("cp.async.commit_group;" ::: "memory");
}
template <int N>
__device__ __forceinline__ void cp_wait() {
    asm volatile("cp.async.wait_group %0;" :: "n"(N) : "memory");
}
__device__ __forceinline__ void ldsm4(uint32_t& r0, uint32_t& r1, uint32_t& r2,
                                      uint32_t& r3, uint32_t a) {
    asm volatile("ldmatrix.sync.aligned.m8n8.x4.shared.b16 {%0,%1,%2,%3}, [%4];"
                 : "=r"(r0), "=r"(r1), "=r"(r2), "=r"(r3) : "r"(a));
}
__device__ __forceinline__ void mma16816(float& c0, float& c1, float& c2, float& c3,
                                         uint32_t a0, uint32_t a1, uint32_t a2,
                                         uint32_t a3, uint32_t b0, uint32_t b1) {
    asm volatile(
        "mma.sync.aligned.m16n8k16.row.col.f32.f16.f16.f32 "
        "{%0,%1,%2,%3}, {%4,%5,%6,%7}, {%8,%9}, {%0,%1,%2,%3};"
        : "+f"(c0), "+f"(c1), "+f"(c2), "+f"(c3)
        : "r"(a0), "r"(a1), "r"(a2), "r"(a3), "r"(b0), "r"(b1));
}

// ---------------- SMEM staging layout (swizzled, no padding) ----------------
// Row = 32 halves = 64B = 4 chunks of 16B. Chunk stored at (c ^ ((row>>1)&3)).
// A_hi: 128 rows (8KB). B_hi: 64 rows (4KB). B_lo: 64 rows (4KB).
constexpr int O_AHI = 0;
constexpr int O_BHI = 8192;
constexpr int O_BLO = 12288;
constexpr int STAGE = 16384;
constexpr int SMEM_TOTAL = 49152;           // 2 stages + epilogue headroom
constexpr int CSTR = 132;                   // C smem row stride (floats)

__device__ __forceinline__ uint32_t swz(int row, int chunk) {
    return (uint32_t)(row * 64 + ((chunk ^ ((row >> 1) & 3)) << 4));
}

// ================= tensor-core GEMM =================
// D[hw 128, o 64] = A[hw, K] * B[o, K]^T, K=256.
// PASSES==2: A_hi*(B_hi + B_lo) — corrects W quantization only.
// PASSES==1: plain fp16 A_hi*B_hi.
// 128 threads, 4 warps (2m x 2n), warp tile 64x32, 2-stage cp.async, 4 CTAs/SM.
template <int EPI, int PASSES>
__global__ __launch_bounds__(128, 4) void mma_gemm(const __half* __restrict__ Ahig,
                                                   const __half* __restrict__ Bhig,
                                                   const __half* __restrict__ Blog,
                                                   const float* __restrict__ bias,
                                                   float* __restrict__ Y) {
    extern __shared__ __align__(1024) char smem[];
    const uint32_t sb = smem_u32(smem);
    const int tid  = threadIdx.x;
    const int wid  = tid >> 5;
    const int lane = tid & 31;
    const int wm = wid & 1;     // warp m tile (64 rows)
    const int wn = wid >> 1;    // warp n tile (32 cols)

    const int slab = blockIdx.z;
    const int hw0  = blockIdx.x * 128;
    const int n0   = blockIdx.y * 64;

    const __half* ah = Ahig + ((size_t)slab * HW + hw0) * 256;
    const __half* bh = Bhig + (size_t)n0 * 256;
    const __half* bl = (PASSES == 2) ? Blog + (size_t)n0 * 256 : bh;

    // hoisted ldmatrix base addresses (kk=0, stage 0); XOR-linear swizzle:
    // kk=1 -> ^0x20, B frag2 -> ^0x10, B lo -> +4096, stage -> +so
    const int rowA0 = wm * 64 + (lane & 15);
    const int chA   = lane >> 4;
    const int rowB  = wn * 32 + lane;
    const uint32_t adrA[4] = {
        sb + O_AHI + swz(rowA0,      chA),
        sb + O_AHI + swz(rowA0 + 16, chA),
        sb + O_AHI + swz(rowA0 + 32, chA),
        sb + O_AHI + swz(rowA0 + 48, chA)};
    const uint32_t adrB = sb + O_BHI + swz(rowB, 0);

    float acc[4][4][4];
#pragma unroll
    for (int mt = 0; mt < 4; mt++)
#pragma unroll
        for (int nt = 0; nt < 4; nt++)
#pragma unroll
            for (int r = 0; r < 4; r++) acc[mt][nt][r] = 0.0f;

    // cp.async mapping: row rA (+32v), chunk sA
    const int rA = tid >> 2, sA = tid & 3;
    const int rswIO = (rA >> 1) & 3;
    const uint32_t soIO = (uint32_t)(rA * 64 + ((sA ^ rswIO) << 4));

    auto issue = [&](int kt, int s) {
        const uint32_t base = sb + s * STAGE;
        const int kbase = kt * 32;
#pragma unroll
        for (int v = 0; v < 4; v++) {       // A rows rA + 32v
            const uint32_t so = soIO + (uint32_t)(v * 2048);
            const size_t go = (size_t)(rA + 32 * v) * 256 + kbase + sA * 8;
            cp16(base + O_AHI + so, ah + go);
        }
#pragma unroll
        for (int v = 0; v < 2; v++) {       // B rows rA + 32v
            const uint32_t so = soIO + (uint32_t)(v * 2048);
            const size_t go = (size_t)(rA + 32 * v) * 256 + kbase + sA * 8;
            cp16(base + O_BHI + so, bh + go);
            if (PASSES == 2) cp16(base + O_BLO + so, bl + go);
        }
    };

    issue(0, 0);
    cp_commit();

    uint32_t so = 0;   // stage offset, toggles 0 <-> STAGE
    for (int kt = 0; kt < 8; kt++) {
        if (kt < 7) {
            issue(kt + 1, (kt + 1) & 1);
            cp_commit();
            cp_wait<1>();
        } else {
            cp_wait<0>();
        }
        __syncthreads();

#pragma unroll
        for (int kk = 0; kk < 2; kk++) {
            const uint32_t kx = (uint32_t)(kk << 5);   // kk=1 -> ^0x20
            uint32_t ahi[4][4];
            uint32_t b0h[4], b1h[4];
#pragma unroll
            for (int mt = 0; mt < 4; mt++)
                ldsm4(ahi[mt][0], ahi[mt][1], ahi[mt][2], ahi[mt][3],
                      (adrA[mt] ^ kx) + so);
            const uint32_t bb = (adrB ^ kx) + so;
            ldsm4(b0h[0], b0h[1], b0h[2], b0h[3], bb);
            ldsm4(b1h[0], b1h[1], b1h[2], b1h[3], bb ^ 0x10);

            if (PASSES == 2) {
                uint32_t b0l[4], b1l[4];
                ldsm4(b0l[0], b0l[1], b0l[2], b0l[3], bb + 4096);
                ldsm4(b1l[0], b1l[1], b1l[2], b1l[3], (bb ^ 0x10) + 4096);
#pragma unroll
                for (int mt = 0; mt < 4; mt++)
#pragma unroll
                    for (int nt = 0; nt < 4; nt++)
                        mma16816(acc[mt][nt][0], acc[mt][nt][1], acc[mt][nt][2],
                                 acc[mt][nt][3], ahi[mt][0], ahi[mt][1],
                                 ahi[mt][2], ahi[mt][3], b0h[nt], b1h[nt]);
#pragma unroll
                for (int mt = 0; mt < 4; mt++)
#pragma unroll
                    for (int nt = 0; nt < 4; nt++)
                        mma16816(acc[mt][nt][0], acc[mt][nt][1], acc[mt][nt][2],
                                 acc[mt][nt][3], ahi[mt][0], ahi[mt][1],
                                 ahi[mt][2], ahi[mt][3], b0l[nt], b1l[nt]);
            } else {
#pragma unroll
                for (int mt = 0; mt < 4; mt++)
#pragma unroll
                    for (int nt = 0; nt < 4; nt++)
                        mma16816(acc[mt][nt][0], acc[mt][nt][1], acc[mt][nt][2],
                                 acc[mt][nt][3], ahi[mt][0], ahi[mt][1],
                                 ahi[mt][2], ahi[mt][3], b0h[nt], b1h[nt]);
            }
        }
        __syncthreads();
        so ^= (uint32_t)STAGE;
    }

    // ---------------- epilogue: transpose through SMEM ----------------
    float* cs = (float*)smem;   // [64 n][CSTR m]
#pragma unroll
    for (int mt = 0; mt < 4; mt++)
#pragma unroll
        for (int nt = 0; nt < 4; nt++) {
            const int n = wn * 32 + nt * 8 + (lane & 3) * 2;
            const int m = wm * 64 + mt * 16 + (lane >> 2);
            cs[n * CSTR + m]           = acc[mt][nt][0];
            cs[(n + 1) * CSTR + m]     = acc[mt][nt][1];
            cs[n * CSTR + m + 8]       = acc[mt][nt][2];
            cs[(n + 1) * CSTR + m + 8] = acc[mt][nt][3];
        }
    __syncthreads();

    const int b_ = slab >> 4, t_ = slab & 15;
#pragma unroll
    for (int r = 0; r < 16; r++) {
        const int n = wid * 16 + r;
        const int o = n0 + n;
        float4 v = *(const float4*)&cs[n * CSTR + lane * 4];
        const float bv = bias[o];
        if (EPI == 0) {
            const int which = o >> 8;
            const int head  = (o >> 5) & 7;
            const int d     = o & 31;
            float* dst = (which == 0) ? g_q : (which == 1 ? g_k : g_v);
            const float sc = (which == 0) ? QSCALE : 1.0f;
            v.x = (v.x + bv) * sc; v.y = (v.y + bv) * sc;
            v.z = (v.z + bv) * sc; v.w = (v.w + bv) * sc;
            const size_t off =
                ((size_t)(((b_ * 8 + head) * 16 + t_) * 32 + d)) * 1024 + hw0 + lane * 4;
            *(float4*)(dst + off) = v;
        } else {
            v.x += bv; v.y += bv; v.z += bv; v.w += bv;
            *(float4*)(Y + ((size_t)slab * 256 + o) * 1024 + hw0 + lane * 4) = v;
        }
    }
}

// ================= split / transpose kernels =================
__global__ __launch_bounds__(256) void split_k(const float* __restrict__ s,
                                               __half* __restrict__ hi,
                                               __half* __restrict__ lo, int n) {
    const int i = blockIdx.x * 256 + threadIdx.x;
    if (i < n) {
        const float f = s[i];
        const __half h = __float2half_rn(f);
        hi[i] = h;
        if (lo) lo[i] = __float2half_rn(f - __half2float(h));
    }
}

// x [slab][c][hw] f32 -> g_xhi [slab][hw][c] fp16 (64x64 tiles)
__global__ __launch_bounds__(256) void split_x_k(const float* __restrict__ x) {
    __shared__ float ts[64][65];
    const int slab = blockIdx.z;
    const int c0 = blockIdx.y * 64;
    const int h0 = blockIdx.x * 64;
    const int tid = threadIdx.x;
    const int r = tid >> 2;
    const int q4 = tid & 3;

    const float* src = x + ((size_t)slab * 256 + c0 + r) * 1024 + h0 + q4 * 16;
#pragma unroll
    for (int j = 0; j < 4; j++) {
        const float4 v = *(const float4*)(src + j * 4);
        ts[r][q4 * 16 + j * 4 + 0] = v.x;
        ts[r][q4 * 16 + j * 4 + 1] = v.y;
        ts[r][q4 * 16 + j * 4 + 2] = v.z;
        ts[r][q4 * 16 + j * 4 + 3] = v.w;
    }
    __syncthreads();

    __half hb[16];
#pragma unroll
    for (int j = 0; j < 16; j++)
        hb[j] = __float2half_rn(ts[q4 * 16 + j][r]);
    const size_t o = ((size_t)slab * 1024 + h0 + r) * 256 + c0 + q4 * 16;
    *(uint4*)(g_xhi + o)     = ((uint4*)hb)[0];
    *(uint4*)(g_xhi + o + 8) = ((uint4*)hb)[1];
}

// ================= attention (T=16), f32 in, fp16 out =================
__device__ __forceinline__ unsigned long long pack2(float lo, float hi) {
    unsigned long long r;
    asm("mov.b64 %0, {%1, %2};" : "=l"(r) : "f"(lo), "f"(hi));
    return r;
}
__device__ __forceinline__ void unpack2(unsigned long long p, float& lo, float& hi) {
    asm("mov.b64 {%0, %1}, %2;" : "=f"(lo), "=f"(hi) : "l"(p));
}
__device__ __forceinline__ unsigned long long ffma2(unsigned long long a,
                                                    unsigned long long b,
                                                    unsigned long long c) {
    unsigned long long d;
    asm("fma.rn.f32x2 %0, %1, %2, %3;" : "=l"(d) : "l"(a), "l"(b), "l"(c));
    return d;
}

constexpr int KVP = 512 + 4;
__global__ __launch_bounds__(128) void attn_k(const float* __restrict__ rel_pos) {
    __shared__ __align__(16) float k_s[8][KVP];
    __shared__ __align__(16) float v_s[8][KVP];

    const int bh  = blockIdx.y;
    const int hw0 = blockIdx.x * 8;
    const int tid = threadIdx.x;
    const int hwl = tid & 7;
    const int i   = tid >> 3;

    const size_t ubase = (size_t)bh * 512 * HW;

    for (int e = tid; e < 4096; e += 128) {
        const int td = e >> 3;
        const int hw = e & 7;
        k_s[hw][td] = g_k[ubase + (size_t)td * HW + hw0 + hw];
        v_s[hw][td] = g_v[ubase + (size_t)td * HW + hw0 + hw];
    }
    __syncthreads();

    unsigned long long qp[16];
    const size_t qbase = ubase + (size_t)i * 32 * HW + hw0 + hwl;
#pragma unroll
    for (int c = 0; c < 16; c++)
        qp[c] = pack2(g_q[qbase + (size_t)(2 * c) * HW],
                      g_q[qbase + (size_t)(2 * c + 1) * HW]);

    const int head = bh & 7;
    const float* rp = rel_pos + head * 256 + i * 16;

    float s[16];
#pragma unroll
    for (int j = 0; j < 16; j++) {
        const ulonglong2* kp = (const ulonglong2*)&k_s[hwl][j * 32];
        unsigned long long acc = 0ull;
#pragma unroll
        for (int c = 0; c < 8; c++) {
            const ulonglong2 kk = kp[c];
            acc = ffma2(qp[2 * c],     kk.x, acc);
            acc = ffma2(qp[2 * c + 1], kk.y, acc);
        }
        float lo, hi;
        unpack2(acc, lo, hi);
        s[j] = lo + hi + rp[j];
    }

    float mx = s[0];
#pragma unroll
    for (int j = 1; j < 16; j++) mx = fmaxf(mx, s[j]);
    float sum = 0.0f;
#pragma unroll
    for (int j = 0; j < 16; j++) { s[j] = expf(s[j] - mx); sum += s[j]; }
    const float inv = 1.0f / sum;

    unsigned long long o2[16];
#pragma unroll
    for (int c = 0; c < 16; c++) o2[c] = 0ull;
#pragma unroll
    for (int j = 0; j < 16; j++) {
        const unsigned long long pp = pack2(s[j], s[j]);
        const ulonglong2* vp = (const ulonglong2*)&v_s[hwl][j * 32];
#pragma unroll
        for (int c = 0; c < 8; c++) {
            const ulonglong2 vv = vp[c];
            o2[2 * c]     = ffma2(pp, vv.x, o2[2 * c]);
            o2[2 * c + 1] = ffma2(pp, vv.y, o2[2 * c + 1]);
        }
    }

    // write fp16 output [slab][hw][e]
    const int b_ = bh >> 3;
    const size_t obase =
        ((size_t)((b_ * 16 + i)) * 1024 + hw0 + hwl) * 256 + head * 32;
#pragma unroll
    for (int c = 0; c < 16; c++) {
        float lo, hi;
        unpack2(o2[c], lo, hi);
        ((__half2*)(g_ohi + obase))[c] =
            __halves2half2(__float2half_rn(lo * inv), __float2half_rn(hi * inv));
    }
}

// ================= host =================
extern "C" void kernel_launch(void* const* d_in, const int* in_sizes, int n_in,
                              void* d_out, int out_size) {
    const float* x       = (const float*)d_in[0];
    const float* rel_pos = (const float*)d_in[1];
    const float* w_qkv   = (const float*)d_in[2];
    const float* b_qkv   = (const float*)d_in[3];
    const float* w_out   = (const float*)d_in[4];
    const float* b_out   = (const float*)d_in[5];
    float* y = (float*)d_out;

    cudaFuncSetAttribute(mma_gemm<0, 2>, cudaFuncAttributeMaxDynamicSharedMemorySize, SMEM_TOTAL);
    cudaFuncSetAttribute(mma_gemm<1, 1>, cudaFuncAttributeMaxDynamicSharedMemorySize, SMEM_TOTAL);

    __half *xhi, *whi, *wlo, *wohi, *ohi;
    cudaGetSymbolAddress((void**)&xhi, g_xhi);
    cudaGetSymbolAddress((void**)&whi, g_whi);
    cudaGetSymbolAddress((void**)&wlo, g_wlo);
    cudaGetSymbolAddress((void**)&wohi, g_wohi);
    cudaGetSymbolAddress((void**)&ohi, g_ohi);

    // precision splits (weights only; X goes straight to fp16)
    split_k<<<768, 256>>>(w_qkv, whi, wlo, 768 * 256);
    split_k<<<256, 256>>>(w_out, wohi, nullptr, 256 * 256);
    split_x_k<<<dim3(16, 4, 64), 256>>>(x);

    // QKV projection (2-pass, W corrected): grid = (hw 8, o 12, slabs 64)
    mma_gemm<0, 2><<<dim3(8, 12, 64), 128, SMEM_TOTAL>>>(xhi, whi, wlo, b_qkv, nullptr);
    // attention
    attn_k<<<dim3(128, 32), 128>>>(rel_pos);
    // output projection (single fp16 pass): grid = (8, 4, 64)
    mma_gemm<1, 1><<<dim3(8, 4, 64), 128, SMEM_TOTAL>>>(ohi, wohi, nullptr, b_out, y);
}

// round 11
// speedup vs baseline: 1.4412x; 1.0058x over previous
#include <cuda_runtime.h>
#include <cuda_fp16.h>
#include <cstdint>

// ---------------- problem constants ----------------
constexpr int B_    = 4;
constexpr int T_    = 16;
constexpr int C_    = 256;
constexpr int HEADS = 8;
constexpr int DH    = 32;
constexpr int HW    = 1024;       // 32*32
constexpr int NSLAB = B_ * T_;    // 64
constexpr float QSCALE = 0.17677669529663687f;

// ---------------- scratch (__device__ globals) ----------------
__device__ __half g_xhi[NSLAB * HW * C_];   // [slab][hw][c]
__device__ __half g_whi[768 * 256];         // [o][c]
__device__ __half g_wlo[768 * 256];
__device__ __half g_wohi[256 * 256];
__device__ __half g_q[B_ * HEADS * T_ * DH * HW];  // fp16 [b][head][t][d][hw]
__device__ __half g_k[B_ * HEADS * T_ * DH * HW];
__device__ __half g_v[B_ * HEADS * T_ * DH * HW];
__device__ __half g_ohi[NSLAB * HW * C_];   // [slab][hw][e]

// ---------------- PTX helpers ----------------
__device__ __forceinline__ uint32_t smem_u32(const void* p) {
    uint32_t a;
    asm("{ .reg .u64 t; cvta.to.shared.u64 t, %1; cvt.u32.u64 %0, t; }" : "=r"(a) : "l"(p));
    return a;
}
__device__ __forceinline__ void cp16(uint32_t s, const void* g) {
    asm volatile("cp.async.cg.shared.global [%0], [%1], 16;" :: "r"(s), "l"(g) : "memory");
}
__device__ __forceinline__ void cp_commit() {
    asm volatile("cp.async.commit_group;" ::: "memory");
}
template <int N>
__device__ __forceinline__ void cp_wait() {
    asm volatile("cp.async.wait_group %0;" :: "n"(N) : "memory");
}
__device__ __forceinline__ void ldsm4(uint32_t& r0, uint32_t& r1, uint32_t& r2,
                                      uint32_t& r3, uint32_t a) {
    asm volatile("ldmatrix.sync.aligned.m8n8.x4.shared.b16 {%0,%1,%2,%3}, [%4];"
                 : "=r"(r0), "=r"(r1), "=r"(r2), "=r"(r3) : "r"(a));
}
__device__ __forceinline__ void mma16816(float& c0, float& c1, float& c2, float& c3,
                                         uint32_t a0, uint32_t a1, uint32_t a2,
                                         uint32_t a3, uint32_t b0, uint32_t b1) {
    asm volatile(
        "mma.sync.aligned.m16n8k16.row.col.f32.f16.f16.f32 "
        "{%0,%1,%2,%3}, {%4,%5,%6,%7}, {%8,%9}, {%0,%1,%2,%3};"
        : "+f"(c0), "+f"(c1), "+f"(c2), "+f"(c3)
        : "r"(a0), "r"(a1), "r"(a2), "r"(a3), "r"(b0), "r"(b1));
}

// ---------------- SMEM staging layout (swizzled, no padding) ----------------
constexpr int O_AHI = 0;
constexpr int O_BHI = 8192;
constexpr int O_BLO = 12288;
constexpr int STAGE = 16384;
constexpr int SMEM_TOTAL = 49152;           // 2 stages + epilogue headroom
constexpr int CSTR = 132;                   // C smem row stride (floats)

__device__ __forceinline__ uint32_t swz(int row, int chunk) {
    return (uint32_t)(row * 64 + ((chunk ^ ((row >> 1) & 3)) << 4));
}

// ================= tensor-core GEMM =================
// D[hw 128, o 64] = A[hw, K] * B[o, K]^T, K=256.
// PASSES==2: A_hi*(B_hi + B_lo). PASSES==1: plain fp16.
// EPI 0: q/k/v fp16 epilogue. EPI 1: +bias -> f32 Y.
template <int EPI, int PASSES>
__global__ __launch_bounds__(128, 4) void mma_gemm(const __half* __restrict__ Ahig,
                                                   const __half* __restrict__ Bhig,
                                                   const __half* __restrict__ Blog,
                                                   const float* __restrict__ bias,
                                                   float* __restrict__ Y) {
    extern __shared__ __align__(1024) char smem[];
    const uint32_t sb = smem_u32(smem);
    const int tid  = threadIdx.x;
    const int wid  = tid >> 5;
    const int lane = tid & 31;
    const int wm = wid & 1;     // warp m tile (64 rows)
    const int wn = wid >> 1;    // warp n tile (32 cols)

    const int slab = blockIdx.z;
    const int hw0  = blockIdx.x * 128;
    const int n0   = blockIdx.y * 64;

    const __half* ah = Ahig + ((size_t)slab * HW + hw0) * 256;
    const __half* bh = Bhig + (size_t)n0 * 256;
    const __half* bl = (PASSES == 2) ? Blog + (size_t)n0 * 256 : bh;

    const int rowA0 = wm * 64 + (lane & 15);
    const int chA   = lane >> 4;
    const int rowB  = wn * 32 + lane;
    const uint32_t adrA[4] = {
        sb + O_AHI + swz(rowA0,      chA),
        sb + O_AHI + swz(rowA0 + 16, chA),
        sb + O_AHI + swz(rowA0 + 32, chA),
        sb + O_AHI + swz(rowA0 + 48, chA)};
    const uint32_t adrB = sb + O_BHI + swz(rowB, 0);

    float acc[4][4][4];
#pragma unroll
    for (int mt = 0; mt < 4; mt++)
#pragma unroll
        for (int nt = 0; nt < 4; nt++)
#pragma unroll
            for (int r = 0; r < 4; r++) acc[mt][nt][r] = 0.0f;

    const int rA = tid >> 2, sA = tid & 3;
    const int rswIO = (rA >> 1) & 3;
    const uint32_t soIO = (uint32_t)(rA * 64 + ((sA ^ rswIO) << 4));

    auto issue = [&](int kt, int s) {
        const uint32_t base = sb + s * STAGE;
        const int kbase = kt * 32;
#pragma unroll
        for (int v = 0; v < 4; v++) {
            const uint32_t so = soIO + (uint32_t)(v * 2048);
            const size_t go = (size_t)(rA + 32 * v) * 256 + kbase + sA * 8;
            cp16(base + O_AHI + so, ah + go);
        }
#pragma unroll
        for (int v = 0; v < 2; v++) {
            const uint32_t so = soIO + (uint32_t)(v * 2048);
            const size_t go = (size_t)(rA + 32 * v) * 256 + kbase + sA * 8;
            cp16(base + O_BHI + so, bh + go);
            if (PASSES == 2) cp16(base + O_BLO + so, bl + go);
        }
    };

    issue(0, 0);
    cp_commit();

    uint32_t so = 0;
    for (int kt = 0; kt < 8; kt++) {
        if (kt < 7) {
            issue(kt + 1, (kt + 1) & 1);
            cp_commit();
            cp_wait<1>();
        } else {
            cp_wait<0>();
        }
        __syncthreads();

#pragma unroll
        for (int kk = 0; kk < 2; kk++) {
            const uint32_t kx = (uint32_t)(kk << 5);
            uint32_t ahi[4][4];
            uint32_t b0h[4], b1h[4];
#pragma unroll
            for (int mt = 0; mt < 4; mt++)
                ldsm4(ahi[mt][0], ahi[mt][1], ahi[mt][2], ahi[mt][3],
                      (adrA[mt] ^ kx) + so);
            const uint32_t bb = (adrB ^ kx) + so;
            ldsm4(b0h[0], b0h[1], b0h[2], b0h[3], bb);
            ldsm4(b1h[0], b1h[1], b1h[2], b1h[3], bb ^ 0x10);

            if (PASSES == 2) {
                uint32_t b0l[4], b1l[4];
                ldsm4(b0l[0], b0l[1], b0l[2], b0l[3], bb + 4096);
                ldsm4(b1l[0], b1l[1], b1l[2], b1l[3], (bb ^ 0x10) + 4096);
#pragma unroll
                for (int mt = 0; mt < 4; mt++)
#pragma unroll
                    for (int nt = 0; nt < 4; nt++)
                        mma16816(acc[mt][nt][0], acc[mt][nt][1], acc[mt][nt][2],
                                 acc[mt][nt][3], ahi[mt][0], ahi[mt][1],
                                 ahi[mt][2], ahi[mt][3], b0h[nt], b1h[nt]);
#pragma unroll
                for (int mt = 0; mt < 4; mt++)
#pragma unroll
                    for (int nt = 0; nt < 4; nt++)
                        mma16816(acc[mt][nt][0], acc[mt][nt][1], acc[mt][nt][2],
                                 acc[mt][nt][3], ahi[mt][0], ahi[mt][1],
                                 ahi[mt][2], ahi[mt][3], b0l[nt], b1l[nt]);
            } else {
#pragma unroll
                for (int mt = 0; mt < 4; mt++)
#pragma unroll
                    for (int nt = 0; nt < 4; nt++)
                        mma16816(acc[mt][nt][0], acc[mt][nt][1], acc[mt][nt][2],
                                 acc[mt][nt][3], ahi[mt][0], ahi[mt][1],
                                 ahi[mt][2], ahi[mt][3], b0h[nt], b1h[nt]);
            }
        }
        __syncthreads();
        so ^= (uint32_t)STAGE;
    }

    // ---------------- epilogue: transpose through SMEM ----------------
    float* cs = (float*)smem;   // [64 n][CSTR m]
#pragma unroll
    for (int mt = 0; mt < 4; mt++)
#pragma unroll
        for (int nt = 0; nt < 4; nt++) {
            const int n = wn * 32 + nt * 8 + (lane & 3) * 2;
            const int m = wm * 64 + mt * 16 + (lane >> 2);
            cs[n * CSTR + m]           = acc[mt][nt][0];
            cs[(n + 1) * CSTR + m]     = acc[mt][nt][1];
            cs[n * CSTR + m + 8]       = acc[mt][nt][2];
            cs[(n + 1) * CSTR + m + 8] = acc[mt][nt][3];
        }
    __syncthreads();

    const int b_ = slab >> 4, t_ = slab & 15;
#pragma unroll
    for (int r = 0; r < 16; r++) {
        const int n = wid * 16 + r;
        const int o = n0 + n;
        float4 v = *(const float4*)&cs[n * CSTR + lane * 4];
        const float bv = bias[o];
        if (EPI == 0) {
            const int which = o >> 8;
            const int head  = (o >> 5) & 7;
            const int d     = o & 31;
            __half* dst = (which == 0) ? g_q : (which == 1 ? g_k : g_v);
            const float sc = (which == 0) ? QSCALE : 1.0f;
            const __half2 h01 = __halves2half2(__float2half_rn((v.x + bv) * sc),
                                               __float2half_rn((v.y + bv) * sc));
            const __half2 h23 = __halves2half2(__float2half_rn((v.z + bv) * sc),
                                               __float2half_rn((v.w + bv) * sc));
            const size_t off =
                ((size_t)(((b_ * 8 + head) * 16 + t_) * 32 + d)) * 1024 + hw0 + lane * 4;
            uint2 pk;
            pk.x = *(const uint32_t*)&h01;
            pk.y = *(const uint32_t*)&h23;
            *(uint2*)(dst + off) = pk;
        } else {
            v.x += bv; v.y += bv; v.z += bv; v.w += bv;
            *(float4*)(Y + ((size_t)slab * 256 + o) * 1024 + hw0 + lane * 4) = v;
        }
    }
}

// ================= split / transpose kernels =================
__global__ __launch_bounds__(256) void split_k(const float* __restrict__ s,
                                               __half* __restrict__ hi,
                                               __half* __restrict__ lo, int n) {
    const int i = blockIdx.x * 256 + threadIdx.x;
    if (i < n) {
        const float f = s[i];
        const __half h = __float2half_rn(f);
        hi[i] = h;
        if (lo) lo[i] = __float2half_rn(f - __half2float(h));
    }
}

// x [slab][c][hw] f32 -> g_xhi [slab][hw][c] fp16 (64x64 tiles)
__global__ __launch_bounds__(256) void split_x_k(const float* __restrict__ x) {
    __shared__ float ts[64][65];
    const int slab = blockIdx.z;
    const int c0 = blockIdx.y * 64;
    const int h0 = blockIdx.x * 64;
    const int tid = threadIdx.x;
    const int r = tid >> 2;
    const int q4 = tid & 3;

    const float* src = x + ((size_t)slab * 256 + c0 + r) * 1024 + h0 + q4 * 16;
#pragma unroll
    for (int j = 0; j < 4; j++) {
        const float4 v = *(const float4*)(src + j * 4);
        ts[r][q4 * 16 + j * 4 + 0] = v.x;
        ts[r][q4 * 16 + j * 4 + 1] = v.y;
        ts[r][q4 * 16 + j * 4 + 2] = v.z;
        ts[r][q4 * 16 + j * 4 + 3] = v.w;
    }
    __syncthreads();

    __half hb[16];
#pragma unroll
    for (int j = 0; j < 16; j++)
        hb[j] = __float2half_rn(ts[q4 * 16 + j][r]);
    const size_t o = ((size_t)slab * 1024 + h0 + r) * 256 + c0 + q4 * 16;
    *(uint4*)(g_xhi + o)     = ((uint4*)hb)[0];
    *(uint4*)(g_xhi + o + 8) = ((uint4*)hb)[1];
}

// ================= attention (T=16), fp16 in, fp16 out =================
__device__ __forceinline__ unsigned long long pack2(float lo, float hi) {
    unsigned long long r;
    asm("mov.b64 %0, {%1, %2};" : "=l"(r) : "f"(lo), "f"(hi));
    return r;
}
__device__ __forceinline__ void unpack2(unsigned long long p, float& lo, float& hi) {
    asm("mov.b64 {%0, %1}, %2;" : "=f"(lo), "=f"(hi) : "l"(p));
}
__device__ __forceinline__ unsigned long long ffma2(unsigned long long a,
                                                    unsigned long long b,
                                                    unsigned long long c) {
    unsigned long long d;
    asm("fma.rn.f32x2 %0, %1, %2, %3;" : "=l"(d) : "l"(a), "l"(b), "l"(c));
    return d;
}

// hw tile 16, 256 threads (16 i x 16 hwl). k/v staged f32 in dynamic smem
// as [hwl][td] (KVP=516 pad -> conflict-free LDS.128 over d).
constexpr int KVP = 516;
constexpr int ATTN_SMEM = 2 * 16 * KVP * 4;   // 66048 bytes

__global__ __launch_bounds__(256) void attn_k(const float* __restrict__ rel_pos) {
    extern __shared__ __align__(16) float asmem[];
    float* k_s = asmem;                 // [16][KVP]
    float* v_s = asmem + 16 * KVP;

    const int bh  = blockIdx.y;            // b*8 + head
    const int hw0 = blockIdx.x * 16;
    const int tid = threadIdx.x;
    const int hwl = tid & 15;
    const int i   = tid >> 4;              // query t 0..15

    const size_t ubase = (size_t)bh * 512 * HW;

    // fill k_s/v_s: 512 td rows x 16 hw halves (32B/row, full sectors)
#pragma unroll
    for (int it = 0; it < 4; it++) {
        const int slot = tid + 256 * it;   // 0..1023
        const int td  = slot >> 1;
        const int seg = (slot & 1) * 8;    // hw sub-offset 0 / 8
        const size_t go = ubase + (size_t)td * HW + hw0 + seg;
        const uint4 rk = *(const uint4*)(g_k + go);
        const uint4 rv = *(const uint4*)(g_v + go);
        const __half2* hk = (const __half2*)&rk;
        const __half2* hv = (const __half2*)&rv;
#pragma unroll
        for (int c = 0; c < 4; c++) {
            const float2 fk = __half22float2(hk[c]);
            const float2 fv = __half22float2(hv[c]);
            k_s[(seg + 2 * c)     * KVP + td] = fk.x;
            k_s[(seg + 2 * c + 1) * KVP + td] = fk.y;
            v_s[(seg + 2 * c)     * KVP + td] = fv.x;
            v_s[(seg + 2 * c + 1) * KVP + td] = fv.y;
        }
    }
    __syncthreads();

    // q: 32 halves at stride HW (coalesced across the 16-lane hwl groups)
    unsigned long long qp[16];
    const size_t qbase = ubase + (size_t)i * 32 * HW + hw0 + hwl;
#pragma unroll
    for (int c = 0; c < 16; c++)
        qp[c] = pack2(__half2float(g_q[qbase + (size_t)(2 * c) * HW]),
                      __half2float(g_q[qbase + (size_t)(2 * c + 1) * HW]));

    const int head = bh & 7;
    const float* rp = rel_pos + head * 256 + i * 16;

    float s[16];
#pragma unroll
    for (int j = 0; j < 16; j++) {
        const ulonglong2* kp = (const ulonglong2*)&k_s[hwl * KVP + j * 32];
        unsigned long long acc = 0ull;
#pragma unroll
        for (int c = 0; c < 8; c++) {
            const ulonglong2 kk = kp[c];
            acc = ffma2(qp[2 * c],     kk.x, acc);
            acc = ffma2(qp[2 * c + 1], kk.y, acc);
        }
        float lo, hi;
        unpack2(acc, lo, hi);
        s[j] = lo + hi + rp[j];
    }

    float mx = s[0];
#pragma unroll
    for (int j = 1; j < 16; j++) mx = fmaxf(mx, s[j]);
    float sum = 0.0f;
#pragma unroll
    for (int j = 0; j < 16; j++) { s[j] = expf(s[j] - mx); sum += s[j]; }
    const float inv = 1.0f / sum;

    unsigned long long o2[16];
#pragma unroll
    for (int c = 0; c < 16; c++) o2[c] = 0ull;
#pragma unroll
    for (int j = 0; j < 16; j++) {
        const unsigned long long pp = pack2(s[j], s[j]);
        const ulonglong2* vp = (const ulonglong2*)&v_s[hwl * KVP + j * 32];
#pragma unroll
        for (int c = 0; c < 8; c++) {
            const ulonglong2 vv = vp[c];
            o2[2 * c]     = ffma2(pp, vv.x, o2[2 * c]);
            o2[2 * c + 1] = ffma2(pp, vv.y, o2[2 * c + 1]);
        }
    }

    // write fp16 output [slab][hw][e]
    const int b_ = bh >> 3;
    const size_t obase =
        ((size_t)((b_ * 16 + i)) * 1024 + hw0 + hwl) * 256 + head * 32;
#pragma unroll
    for (int c = 0; c < 16; c++) {
        float lo, hi;
        unpack2(o2[c], lo, hi);
        ((__half2*)(g_ohi + obase))[c] =
            __halves2half2(__float2half_rn(lo * inv), __float2half_rn(hi * inv));
    }
}

// ================= host =================
extern "C" void kernel_launch(void* const* d_in, const int* in_sizes, int n_in,
                              void* d_out, int out_size) {
    const float* x       = (const float*)d_in[0];
    const float* rel_pos = (const float*)d_in[1];
    const float* w_qkv   = (const float*)d_in[2];
    const float* b_qkv   = (const float*)d_in[3];
    const float* w_out   = (const float*)d_in[4];
    const float* b_out   = (const float*)d_in[5];
    float* y = (float*)d_out;

    cudaFuncSetAttribute(mma_gemm<0, 2>, cudaFuncAttributeMaxDynamicSharedMemorySize, SMEM_TOTAL);
    cudaFuncSetAttribute(mma_gemm<1, 1>, cudaFuncAttributeMaxDynamicSharedMemorySize, SMEM_TOTAL);
    cudaFuncSetAttribute(attn_k, cudaFuncAttributeMaxDynamicSharedMemorySize, ATTN_SMEM);

    __half *xhi, *whi, *wlo, *wohi, *ohi;
    cudaGetSymbolAddress((void**)&xhi, g_xhi);
    cudaGetSymbolAddress((void**)&whi, g_whi);
    cudaGetSymbolAddress((void**)&wlo, g_wlo);
    cudaGetSymbolAddress((void**)&wohi, g_wohi);
    cudaGetSymbolAddress((void**)&ohi, g_ohi);

    // precision splits (weights only; X goes straight to fp16)
    split_k<<<768, 256>>>(w_qkv, whi, wlo, 768 * 256);
    split_k<<<256, 256>>>(w_out, wohi, nullptr, 256 * 256);
    split_x_k<<<dim3(16, 4, 64), 256>>>(x);

    // QKV projection (2-pass, W corrected): grid = (hw 8, o 12, slabs 64)
    mma_gemm<0, 2><<<dim3(8, 12, 64), 128, SMEM_TOTAL>>>(xhi, whi, wlo, b_qkv, nullptr);
    // attention: grid = (hw tiles 64, b*heads 32), 256 threads
    attn_k<<<dim3(64, 32), 256, ATTN_SMEM>>>(rel_pos);
    // output projection (single fp16 pass): grid = (8, 4, 64)
    mma_gemm<1, 1><<<dim3(8, 4, 64), 128, SMEM_TOTAL>>>(ohi, wohi, nullptr, b_out, y);
}